// round 5
// baseline (speedup 1.0000x reference)
#include <cuda_runtime.h>
#include <stdint.h>

// Problem constants
#define BATCH   512
#define IN_FLAT 1024
#define NEURONS 4096
#define FOCUS   64

// GEMM tiling
#define BM 128
#define BN 128
#define BK 32
#define TPB 256
#define KTILES (IN_FLAT / BK)      // 32
#define STAGES 4
#define STAGE_BYTES 32768          // A 16KB + B 16KB
#define OF_B 16384
#define OF_BIAS (STAGES * STAGE_BYTES)          // 131072
#define SMEM_DYN (OF_BIAS + BN * 4)             // +512 bias

// Dense scratch (device globals: no allocation allowed)
__device__ float g_W [NEURONS * IN_FLAT];   // [N, K], tf32-rounded, densified
__device__ float g_xr[BATCH   * IN_FLAT];   // x rounded-to-nearest tf32

// ---------------------------------------------------------------------------
__device__ __forceinline__ uint32_t smem_u32(const void* p) {
    uint32_t a;
    asm("{ .reg .u64 t; cvta.to.shared.u64 t, %1; cvt.u32.u64 %0, t; }" : "=r"(a) : "l"(p));
    return a;
}
__device__ __forceinline__ float rna_tf32(float f) {
    unsigned u;
    asm("cvt.rna.tf32.f32 %0, %1;" : "=r"(u) : "f"(f));
    return __uint_as_float(u);
}
__device__ __forceinline__ void cp_async16(uint32_t sdst, const void* gsrc) {
    asm volatile("cp.async.cg.shared.global [%0], [%1], 16;"
                 :: "r"(sdst), "l"(__cvta_generic_to_global(gsrc)) : "memory");
}
__device__ __forceinline__ void mma_tf32(float* c, const uint32_t* a, const uint32_t* b) {
    asm volatile(
        "mma.sync.aligned.m16n8k8.row.col.f32.tf32.tf32.f32 "
        "{%0,%1,%2,%3}, {%4,%5,%6,%7}, {%8,%9}, {%0,%1,%2,%3};"
        : "+f"(c[0]), "+f"(c[1]), "+f"(c[2]), "+f"(c[3])
        : "r"(a[0]), "r"(a[1]), "r"(a[2]), "r"(a[3]), "r"(b[0]), "r"(b[1]));
}

// ---------------------------------------------------------------------------
// Prep kernel 1: zero the dense W (16 MB)
__global__ void zero_W() {
    size_t i = (size_t)blockIdx.x * blockDim.x + threadIdx.x;   // 1M float4
    ((float4*)g_W)[i] = make_float4(0.f, 0.f, 0.f, 0.f);
}

// Prep kernel 2: round x to tf32 (RN) -> g_xr
__global__ void round_x(const float* __restrict__ x) {
    size_t i = (size_t)blockIdx.x * blockDim.x + threadIdx.x;   // 131072 float4
    float4 v = ((const float4*)x)[i];
    v.x = rna_tf32(v.x); v.y = rna_tf32(v.y);
    v.z = rna_tf32(v.z); v.w = rna_tf32(v.w);
    ((float4*)g_xr)[i] = v;
}

// Prep kernel 3: scatter-densify weights into g_W[n, k].
// One thread per neuron: same-address atomics from a single thread commit in
// program order -> deterministic.
__global__ void scatter_W(const void* __restrict__ conn_raw,
                          const float* __restrict__ wgt) {
    int n = blockIdx.x * blockDim.x + threadIdx.x;
    if (n >= NEURONS) return;

    const int* c32 = (const int*)conn_raw;
    bool is64 = true;                       // int64 dtype sniff (values < 1024)
    #pragma unroll
    for (int k = 1; k < 64; k += 2) is64 &= (c32[k] == 0);
    const long long* c64 = (const long long*)conn_raw;

    float* row = g_W + (size_t)n * IN_FLAT;
    #pragma unroll 8
    for (int f = 0; f < FOCUS; ++f) {
        int idx = is64 ? (int)c64[(size_t)n * FOCUS + f] : c32[(size_t)n * FOCUS + f];
        atomicAdd(row + idx, rna_tf32(wgt[(size_t)n * FOCUS + f]));
    }
}

// ---------------------------------------------------------------------------
// Main GEMM: out[512,4096] = x_r @ W^T + bias, tf32 mma.sync, cp.async x4.
//
// Fragment-permuted smem: A plane (m16,ks,reg) / B plane (n8,ks,reg), each a
// 32-float lane vector. Mainloop fragment loads are conflict-free LDS.32;
// each 16B gmem chunk lands in one contiguous permuted slot (cp.async-able).
// ---------------------------------------------------------------------------
__global__ void __launch_bounds__(TPB, 1)
gemm_tf32(const float* __restrict__ bias, float* __restrict__ out) {
    extern __shared__ char smb[];
    const uint32_t sbase = smem_u32(smb);

    const int tid  = threadIdx.x;
    const int lane = tid & 31;
    const int wid  = tid >> 5;
    const int wm   = wid & 3;          // warp row (4)
    const int wn   = wid >> 2;         // warp col (2)
    const int n0   = blockIdx.x * BN;
    const int m0   = blockIdx.y * BM;

    if (tid < BN) *(float*)(smb + OF_BIAS + tid * 4) = bias[n0 + tid];

    const float* gA = g_xr + (size_t)m0 * IN_FLAT;
    const float* gB = g_W  + (size_t)n0 * IN_FLAT;

    // per-thread staging coordinates (4 x 16B chunks for each of A and B)
    uint32_t adst[4], bdst[4];
    int      soff[4];
    #pragma unroll
    for (int it = 0; it < 4; ++it) {
        int e   = it * TPB + tid;     // 0..1023 float4 chunks
        int row = e >> 3;             // 0..127
        int c4  = e & 7;              // float4 col within 32-float slab
        soff[it] = row * IN_FLAT + c4 * 4;
        {   // A: reg = half*2 + hi
            int m16 = row >> 4, g = row & 7, hi = (row >> 3) & 1;
            int ks = c4 >> 1, half = c4 & 1, reg = half * 2 + hi;
            adst[it] = (uint32_t)(((m16 * 4 + ks) * 4 + reg) * 128 + g * 16);
        }
        {   // B: reg = c4&1
            int n8 = row >> 3, gn = row & 7;
            int ks = c4 >> 1, reg = c4 & 1;
            bdst[it] = (uint32_t)(OF_B + ((n8 * 4 + ks) * 2 + reg) * 128 + gn * 16);
        }
    }

    auto stage = [&](int kt, int s) {
        uint32_t b = sbase + (uint32_t)s * STAGE_BYTES;
        #pragma unroll
        for (int it = 0; it < 4; ++it) {
            cp_async16(b + adst[it], gA + soff[it] + kt * BK);
            cp_async16(b + bdst[it], gB + soff[it] + kt * BK);
        }
    };

    // prologue: fill STAGES-1 buffers
    #pragma unroll
    for (int s = 0; s < STAGES - 1; ++s) {
        stage(s, s);
        asm volatile("cp.async.commit_group;" ::: "memory");
    }

    float acc[2][8][4] = {};

    for (int kt = 0; kt < KTILES; ++kt) {
        asm volatile("cp.async.wait_group %0;" :: "n"(STAGES - 2) : "memory");
        __syncthreads();

        const char* tb = smb + (size_t)(kt & (STAGES - 1)) * STAGE_BYTES;
        #pragma unroll
        for (int ks = 0; ks < 4; ++ks) {
            uint32_t a[2][4], b[8][2];
            #pragma unroll
            for (int i = 0; i < 2; ++i) {
                const char* p = tb + (((wm * 2 + i) * 4 + ks) * 4) * 128 + lane * 4;
                #pragma unroll
                for (int r = 0; r < 4; ++r) a[i][r] = *(const uint32_t*)(p + r * 128);
            }
            #pragma unroll
            for (int j = 0; j < 8; ++j) {
                const char* p = tb + OF_B + (((wn * 8 + j) * 4 + ks) * 2) * 128 + lane * 4;
                b[j][0] = *(const uint32_t*)p;
                b[j][1] = *(const uint32_t*)(p + 128);
            }
            #pragma unroll
            for (int i = 0; i < 2; ++i)
                #pragma unroll
                for (int j = 0; j < 8; ++j)
                    mma_tf32(acc[i][j], a[i], b[j]);
        }

        int nk = kt + STAGES - 1;
        if (nk < KTILES) stage(nk, nk & (STAGES - 1));
        asm volatile("cp.async.commit_group;" ::: "memory");  // empty group OK in tail
    }

    // epilogue: bias add + coalesced float2 stores
    const int g = lane >> 2, t = lane & 3;
    const float* sb = (const float*)(smb + OF_BIAS) + wn * 64;
    #pragma unroll
    for (int i = 0; i < 2; ++i) {
        #pragma unroll
        for (int hi = 0; hi < 2; ++hi) {
            int row = m0 + wm * 32 + i * 16 + hi * 8 + g;
            float* orow = out + (size_t)row * NEURONS + n0 + wn * 64;
            #pragma unroll
            for (int j = 0; j < 8; ++j) {
                int c = j * 8 + t * 2;
                float2 v = make_float2(acc[i][j][hi * 2 + 0] + sb[c],
                                       acc[i][j][hi * 2 + 1] + sb[c + 1]);
                *(float2*)(orow + c) = v;
            }
        }
    }
}

// ---------------------------------------------------------------------------
extern "C" void kernel_launch(void* const* d_in, const int* in_sizes, int n_in,
                              void* d_out, int out_size) {
    const float* x    = (const float*)d_in[0];
    const void*  conn = d_in[1];                  // int64 (or int32) indices
    const float* wgt  = (const float*)d_in[2];
    const float* bias = (const float*)d_in[3];
    float* out = (float*)d_out;

    cudaFuncSetAttribute(gemm_tf32,
                         cudaFuncAttributeMaxDynamicSharedMemorySize,
                         (int)SMEM_DYN);

    zero_W  <<<2048, 512>>>();                        // 16 MB
    round_x <<<256,  512>>>(x);                       // 2 MB
    scatter_W<<<(NEURONS + 255) / 256, 256>>>(conn, wgt);

    dim3 grid(NEURONS / BN, BATCH / BM);              // 32 x 4 = 128 blocks
    gemm_tf32<<<grid, TPB, SMEM_DYN>>>(bias, out);
}

// round 6
// speedup vs baseline: 2.2768x; 2.2768x over previous
#include <cuda_runtime.h>
#include <stdint.h>

// Problem constants
#define BATCH   512
#define IN_FLAT 1024
#define NEURONS 4096
#define FOCUS   64

// GEMM tiling
#define BM 128
#define BN 128
#define BK 32
#define TPB 512
#define KTILES (IN_FLAT / BK)      // 32
#define STAGES 4
#define STAGE_BYTES 32768          // A 16KB + B 16KB
#define OF_B 16384
#define OF_BIAS (STAGES * STAGE_BYTES)          // 131072
#define SMEM_DYN (OF_BIAS + BN * 4)             // 131584

// Fragment-ordered operands (device globals: no allocation allowed)
// A: [kt 32][m16 32][ks 4][lane 32][reg 4] floats  (2 MB)
// B: [kt 32][n16 256][ks 4][lane 32][reg 4] floats (16 MB)
__device__ float g_xA[BATCH   * IN_FLAT];
__device__ float g_WB[NEURONS * IN_FLAT];

// ---------------------------------------------------------------------------
__device__ __forceinline__ uint32_t smem_u32(const void* p) {
    uint32_t a;
    asm("{ .reg .u64 t; cvta.to.shared.u64 t, %1; cvt.u32.u64 %0, t; }" : "=r"(a) : "l"(p));
    return a;
}
__device__ __forceinline__ float rna_tf32(float f) {
    unsigned u;
    asm("cvt.rna.tf32.f32 %0, %1;" : "=r"(u) : "f"(f));
    return __uint_as_float(u);
}
__device__ __forceinline__ void cp_async16(uint32_t sdst, const void* gsrc) {
    asm volatile("cp.async.cg.shared.global [%0], [%1], 16;"
                 :: "r"(sdst), "l"(__cvta_generic_to_global(gsrc)) : "memory");
}
__device__ __forceinline__ void mma_tf32(float* c, const uint4& a,
                                         uint32_t b0, uint32_t b1) {
    asm volatile(
        "mma.sync.aligned.m16n8k8.row.col.f32.tf32.tf32.f32 "
        "{%0,%1,%2,%3}, {%4,%5,%6,%7}, {%8,%9}, {%0,%1,%2,%3};"
        : "+f"(c[0]), "+f"(c[1]), "+f"(c[2]), "+f"(c[3])
        : "r"(a.x), "r"(a.y), "r"(a.z), "r"(a.w), "r"(b0), "r"(b1));
}

// ---------------------------------------------------------------------------
// Prep 1: round x to tf32-RN and write in A-fragment order.
// chunk c -> (kt, m16, ks, lane); regs = {(ra,k0),(ra+8,k0),(ra,k0+4),(ra+8,k0+4)}
__global__ void round_x_frag(const float* __restrict__ x) {
    int c = blockIdx.x * blockDim.x + threadIdx.x;     // 131072 chunks
    int lane = c & 31, ks = (c >> 5) & 3, m16 = (c >> 7) & 31, kt = c >> 12;
    int ra = m16 * 16 + (lane >> 2);
    int k0 = kt * 32 + ks * 8 + (lane & 3);
    float4 v;
    v.x = rna_tf32(x[(size_t)ra * IN_FLAT + k0]);
    v.y = rna_tf32(x[(size_t)(ra + 8) * IN_FLAT + k0]);
    v.z = rna_tf32(x[(size_t)ra * IN_FLAT + k0 + 4]);
    v.w = rna_tf32(x[(size_t)(ra + 8) * IN_FLAT + k0 + 4]);
    ((float4*)g_xA)[c] = v;
}

// Prep 2: densify W in smem (16 rows/block), write in B-fragment order.
// Replaces zero_W + scatter_W: one 16 MB pass, smem atomics for duplicates.
#define DSTR 1044                          // padded row stride (floats)
#define D_SM_FLOATS (16 * DSTR)            // 16704 floats = 66816 B
__global__ void densify_W(const void* __restrict__ conn_raw,
                          const float* __restrict__ wgt) {
    extern __shared__ float ds[];
    const int tid = threadIdx.x;
    const int n16g = blockIdx.x;           // 0..255

    // zero 16 padded rows
    #pragma unroll
    for (int i = tid; i < D_SM_FLOATS / 4; i += 256)
        ((float4*)ds)[i] = make_float4(0.f, 0.f, 0.f, 0.f);
    __syncthreads();

    // dtype sniff: int64 values < 1024 have zero odd words
    const int* c32 = (const int*)conn_raw;
    bool is64 = true;
    #pragma unroll
    for (int k = 1; k < 64; k += 2) is64 &= (c32[k] == 0);
    const long long* c64 = (const long long*)conn_raw;

    // scatter 16*64 entries (4 per thread) via smem atomics
    #pragma unroll
    for (int i = 0; i < 4; ++i) {
        int e = i * 256 + tid;                       // 0..1023
        int nl = e >> 6, f = e & 63;
        size_t gi = (size_t)(n16g * 16 + nl) * FOCUS + f;
        int idx = is64 ? (int)c64[gi] : c32[gi];
        atomicAdd(ds + nl * DSTR + idx, rna_tf32(wgt[gi]));
    }
    __syncthreads();

    // write out in B-fragment order: [kt][n16g][ks][lane][reg4]
    #pragma unroll
    for (int i = 0; i < 16; ++i) {
        int c   = i * 256 + tid;                     // 0..4095 chunks
        int kt  = c >> 7;
        int rem = c & 127;
        int ks  = rem >> 5, ln = rem & 31;
        int k0  = kt * 32 + ks * 8 + (ln & 3);
        int na  = ln >> 2;
        float4 v;
        v.x = rna_tf32(ds[na * DSTR + k0]);          // j0.b0
        v.y = rna_tf32(ds[na * DSTR + k0 + 4]);      // j0.b1
        v.z = rna_tf32(ds[(na + 8) * DSTR + k0]);    // j1.b0
        v.w = rna_tf32(ds[(na + 8) * DSTR + k0 + 4]);// j1.b1
        ((float4*)g_WB)[(size_t)(kt * 256 + n16g) * 128 + rem] = v;
    }
}

// ---------------------------------------------------------------------------
// Main GEMM: out = x @ W^T + bias. 512 thr, 4x4 warps, 32x32 warp tile,
// linear cp.async staging, LDS.128 fragment loads, m16n8k8 tf32.
// ---------------------------------------------------------------------------
__global__ void __launch_bounds__(TPB, 1)
gemm_tf32(const float* __restrict__ bias, float* __restrict__ out) {
    extern __shared__ char smb[];
    const uint32_t sbase = smem_u32(smb);

    const int tid  = threadIdx.x;
    const int lane = tid & 31;
    const int wid  = tid >> 5;
    const int wm   = wid & 3;          // warp row (4)
    const int wn   = wid >> 2;         // warp col (4)
    const int n0   = blockIdx.x * BN;
    const int m0   = blockIdx.y * BM;

    if (tid < BN) *(float*)(smb + OF_BIAS + tid * 4) = bias[n0 + tid];

    const float4* gA4 = (const float4*)g_xA;
    const float4* gB4 = (const float4*)g_WB;
    const int mSlab = m0 >> 4;         // m16g base (8 tiles)
    const int nSlab = n0 >> 4;         // n16g base (8 tiles)

    auto stage = [&](int kt, int s) {
        uint32_t db = sbase + (uint32_t)s * STAGE_BYTES;
        size_t baseA = ((size_t)kt * 32  + mSlab) * 128;
        size_t baseB = ((size_t)kt * 256 + nSlab) * 128;
        cp_async16(db + (uint32_t)tid * 16,                 gA4 + baseA + tid);
        cp_async16(db + (uint32_t)(512 + tid) * 16,         gA4 + baseA + 512 + tid);
        cp_async16(db + OF_B + (uint32_t)tid * 16,          gB4 + baseB + tid);
        cp_async16(db + OF_B + (uint32_t)(512 + tid) * 16,  gB4 + baseB + 512 + tid);
    };

    #pragma unroll
    for (int s = 0; s < STAGES - 1; ++s) {
        stage(s, s);
        asm volatile("cp.async.commit_group;" ::: "memory");
    }

    float acc[2][2][2][4] = {};   // [m16 i][n16 t][n8 j][c-reg]

    for (int kt = 0; kt < KTILES; ++kt) {
        asm volatile("cp.async.wait_group %0;" :: "n"(STAGES - 2) : "memory");
        __syncthreads();

        const char* tb = smb + (size_t)(kt & (STAGES - 1)) * STAGE_BYTES;
        const char* ta0 = tb +          ((wm * 2 + 0) * 4) * 512 + lane * 16;
        const char* ta1 = tb +          ((wm * 2 + 1) * 4) * 512 + lane * 16;
        const char* tb0 = tb + OF_B + ((wn * 2 + 0) * 4) * 512 + lane * 16;
        const char* tb1 = tb + OF_B + ((wn * 2 + 1) * 4) * 512 + lane * 16;

        #pragma unroll
        for (int ks = 0; ks < 4; ++ks) {
            uint4 a0 = *(const uint4*)(ta0 + ks * 512);
            uint4 a1 = *(const uint4*)(ta1 + ks * 512);
            uint4 b0 = *(const uint4*)(tb0 + ks * 512);
            uint4 b1 = *(const uint4*)(tb1 + ks * 512);
            mma_tf32(acc[0][0][0], a0, b0.x, b0.y);
            mma_tf32(acc[0][0][1], a0, b0.z, b0.w);
            mma_tf32(acc[0][1][0], a0, b1.x, b1.y);
            mma_tf32(acc[0][1][1], a0, b1.z, b1.w);
            mma_tf32(acc[1][0][0], a1, b0.x, b0.y);
            mma_tf32(acc[1][0][1], a1, b0.z, b0.w);
            mma_tf32(acc[1][1][0], a1, b1.x, b1.y);
            mma_tf32(acc[1][1][1], a1, b1.z, b1.w);
        }

        int nk = kt + STAGES - 1;
        if (nk < KTILES) stage(nk, nk & (STAGES - 1));
        asm volatile("cp.async.commit_group;" ::: "memory");
    }

    // epilogue: bias add + float2 stores
    const int g = lane >> 2, q = lane & 3;
    const float* sb = (const float*)(smb + OF_BIAS);
    #pragma unroll
    for (int i = 0; i < 2; ++i) {
        #pragma unroll
        for (int hi = 0; hi < 2; ++hi) {
            int row = m0 + (wm * 2 + i) * 16 + hi * 8 + g;
            float* orow = out + (size_t)row * NEURONS + n0;
            #pragma unroll
            for (int t = 0; t < 2; ++t)
                #pragma unroll
                for (int j = 0; j < 2; ++j) {
                    int col = (wn * 2 + t) * 16 + j * 8 + q * 2;
                    float2 v = make_float2(acc[i][t][j][hi * 2 + 0] + sb[col],
                                           acc[i][t][j][hi * 2 + 1] + sb[col + 1]);
                    *(float2*)(orow + col) = v;
                }
        }
    }
}

// ---------------------------------------------------------------------------
extern "C" void kernel_launch(void* const* d_in, const int* in_sizes, int n_in,
                              void* d_out, int out_size) {
    const float* x    = (const float*)d_in[0];
    const void*  conn = d_in[1];                  // int64 (or int32) indices
    const float* wgt  = (const float*)d_in[2];
    const float* bias = (const float*)d_in[3];
    float* out = (float*)d_out;

    cudaFuncSetAttribute(gemm_tf32,
                         cudaFuncAttributeMaxDynamicSharedMemorySize, SMEM_DYN);
    cudaFuncSetAttribute(densify_W,
                         cudaFuncAttributeMaxDynamicSharedMemorySize,
                         D_SM_FLOATS * 4);

    round_x_frag<<<512, 256>>>(x);                       // 2 MB, A-fragment order
    densify_W<<<256, 256, D_SM_FLOATS * 4>>>(conn, wgt); // 16 MB, B-fragment order

    dim3 grid(NEURONS / BN, BATCH / BM);                 // 32 x 4 = 128 blocks
    gemm_tf32<<<grid, TPB, SMEM_DYN>>>(bias, out);
}

// round 7
// speedup vs baseline: 2.3411x; 1.0282x over previous
#include <cuda_runtime.h>
#include <stdint.h>

// Problem constants
#define BATCH   512
#define IN_FLAT 1024
#define NEURONS 4096
#define FOCUS   64

// GEMM tiling
#define BM 128
#define BN 128
#define BK 32
#define TPB 256                    // 8 warps, warp tile 32x64 (4m x 2n)
#define KTILES (IN_FLAT / BK)      // 32
#define STAGES 4
#define STAGE_BYTES 32768          // A 16KB + B 16KB
#define OF_B 16384
#define OF_BIAS (STAGES * STAGE_BYTES)          // 131072
#define SMEM_DYN (OF_BIAS + BN * 4)             // 131584

// Fragment-ordered operands (device globals: no allocation allowed)
// A: [kt 32][m16 32][ks 4][lane 32] float4  (2 MB)
// B: [kt 32][n16 256][ks 4][lane 32] float4 (16 MB)
__device__ float g_xA[BATCH   * IN_FLAT];
__device__ float g_WB[NEURONS * IN_FLAT];

// ---------------------------------------------------------------------------
__device__ __forceinline__ uint32_t smem_u32(const void* p) {
    uint32_t a;
    asm("{ .reg .u64 t; cvta.to.shared.u64 t, %1; cvt.u32.u64 %0, t; }" : "=r"(a) : "l"(p));
    return a;
}
__device__ __forceinline__ float rna_tf32(float f) {
    unsigned u;
    asm("cvt.rna.tf32.f32 %0, %1;" : "=r"(u) : "f"(f));
    return __uint_as_float(u);
}
__device__ __forceinline__ void cp_async16(uint32_t sdst, const void* gsrc) {
    asm volatile("cp.async.cg.shared.global [%0], [%1], 16;"
                 :: "r"(sdst), "l"(__cvta_generic_to_global(gsrc)) : "memory");
}
__device__ __forceinline__ void mma_tf32(float* c, const uint4& a,
                                         uint32_t b0, uint32_t b1) {
    asm volatile(
        "mma.sync.aligned.m16n8k8.row.col.f32.tf32.tf32.f32 "
        "{%0,%1,%2,%3}, {%4,%5,%6,%7}, {%8,%9}, {%0,%1,%2,%3};"
        : "+f"(c[0]), "+f"(c[1]), "+f"(c[2]), "+f"(c[3])
        : "r"(a.x), "r"(a.y), "r"(a.z), "r"(a.w), "r"(b0), "r"(b1));
}

// ---------------------------------------------------------------------------
// Prep 1 (v2): round x to tf32-RN, write A-fragment order. Coalesced both ways
// via a 16-row smem tile (pad stride 1028 -> conflict-free fragment reads).
#define RSTR 1028                              // floats; 1028 % 32 = 4
#define R_SM_BYTES (16 * RSTR * 4)             // 65792
__global__ void round_x_frag(const float* __restrict__ x) {
    extern __shared__ float ds[];
    const int tid  = threadIdx.x;
    const int lane = tid & 31;
    const int w    = tid >> 5;                 // 8 warps
    const int m16  = blockIdx.x;               // 0..31

    // stage rows w and w+8 (coalesced 128B loads, rna applied once here)
    #pragma unroll
    for (int h = 0; h < 2; ++h) {
        int r = w + h * 8;
        const float4* src = (const float4*)(x + (size_t)(m16 * 16 + r) * IN_FLAT);
        float4* dst = (float4*)(ds + r * RSTR);
        #pragma unroll
        for (int j = 0; j < 8; ++j) {
            float4 v = src[j * 32 + lane];
            v.x = rna_tf32(v.x); v.y = rna_tf32(v.y);
            v.z = rna_tf32(v.z); v.w = rna_tf32(v.w);
            dst[j * 32 + lane] = v;
        }
    }
    __syncthreads();

    // write 4096 fragment chunks (16/thread), coalesced STG.128
    #pragma unroll
    for (int i = 0; i < 16; ++i) {
        int e  = i * 256 + tid;                // 0..4095
        int kt = e >> 7, ks = (e >> 5) & 3, ln = e & 31;
        int ra = ln >> 2;
        int k0 = kt * 32 + ks * 8 + (ln & 3);
        float4 v;
        v.x = ds[ra * RSTR + k0];
        v.y = ds[(ra + 8) * RSTR + k0];
        v.z = ds[ra * RSTR + k0 + 4];
        v.w = ds[(ra + 8) * RSTR + k0 + 4];
        ((float4*)g_xA)[((size_t)(kt * 32 + m16) * 4 + ks) * 32 + ln] = v;
    }
}

// Prep 2: densify W in smem (16 rows/block), write in B-fragment order.
#define DSTR 1044                          // padded row stride (floats)
#define D_SM_FLOATS (16 * DSTR)            // 66816 B
__global__ void densify_W(const void* __restrict__ conn_raw,
                          const float* __restrict__ wgt) {
    extern __shared__ float ds[];
    const int tid = threadIdx.x;
    const int n16g = blockIdx.x;           // 0..255

    #pragma unroll
    for (int i = tid; i < D_SM_FLOATS / 4; i += 256)
        ((float4*)ds)[i] = make_float4(0.f, 0.f, 0.f, 0.f);
    __syncthreads();

    const int* c32 = (const int*)conn_raw;
    bool is64 = true;                      // int64 dtype sniff (values < 1024)
    #pragma unroll
    for (int k = 1; k < 64; k += 2) is64 &= (c32[k] == 0);
    const long long* c64 = (const long long*)conn_raw;

    #pragma unroll
    for (int i = 0; i < 4; ++i) {
        int e = i * 256 + tid;                       // 0..1023
        int nl = e >> 6, f = e & 63;
        size_t gi = (size_t)(n16g * 16 + nl) * FOCUS + f;
        int idx = is64 ? (int)c64[gi] : c32[gi];
        atomicAdd(ds + nl * DSTR + idx, rna_tf32(wgt[gi]));
    }
    __syncthreads();

    #pragma unroll
    for (int i = 0; i < 16; ++i) {
        int c   = i * 256 + tid;                     // 0..4095 chunks
        int kt  = c >> 7;
        int rem = c & 127;
        int ks  = rem >> 5, ln = rem & 31;
        int k0  = kt * 32 + ks * 8 + (ln & 3);
        int na  = ln >> 2;
        float4 v;
        v.x = rna_tf32(ds[na * DSTR + k0]);
        v.y = rna_tf32(ds[na * DSTR + k0 + 4]);
        v.z = rna_tf32(ds[(na + 8) * DSTR + k0]);
        v.w = rna_tf32(ds[(na + 8) * DSTR + k0 + 4]);
        ((float4*)g_WB)[(size_t)(kt * 256 + n16g) * 128 + rem] = v;
    }
}

// ---------------------------------------------------------------------------
// Main GEMM: out = x @ W^T + bias. 256 thr (8 warps), warp tile 32x64,
// tensor-dominant balance, cp.async x4, LDS.128 fragment loads.
// ---------------------------------------------------------------------------
__global__ void __launch_bounds__(TPB, 1)
gemm_tf32(const float* __restrict__ bias, float* __restrict__ out) {
    extern __shared__ char smb[];
    const uint32_t sbase = smem_u32(smb);

    const int tid  = threadIdx.x;
    const int lane = tid & 31;
    const int wid  = tid >> 5;
    const int wm   = wid & 3;          // warp row (4)  -> m16 tiles {2wm, 2wm+1}
    const int wn   = wid >> 2;         // warp col (2)  -> n16 tiles {4wn..4wn+3}
    const int n0   = blockIdx.x * BN;
    const int m0   = blockIdx.y * BM;

    if (tid < BN) *(float*)(smb + OF_BIAS + tid * 4) = bias[n0 + tid];

    const float4* gA4 = (const float4*)g_xA;
    const float4* gB4 = (const float4*)g_WB;
    const int mSlab = m0 >> 4;
    const int nSlab = n0 >> 4;

    auto stage = [&](int kt, int s) {
        uint32_t db = sbase + (uint32_t)s * STAGE_BYTES;
        size_t baseA = ((size_t)kt * 32  + mSlab) * 128;
        size_t baseB = ((size_t)kt * 256 + nSlab) * 128;
        #pragma unroll
        for (int it = 0; it < 4; ++it) {
            cp_async16(db + (uint32_t)(it * 256 + tid) * 16,
                       gA4 + baseA + it * 256 + tid);
            cp_async16(db + OF_B + (uint32_t)(it * 256 + tid) * 16,
                       gB4 + baseB + it * 256 + tid);
        }
    };

    #pragma unroll
    for (int s = 0; s < STAGES - 1; ++s) {
        stage(s, s);
        asm volatile("cp.async.commit_group;" ::: "memory");
    }

    float acc[2][4][2][4] = {};   // [m16 i][n16 t][n8 j][c-reg]

    for (int kt = 0; kt < KTILES; ++kt) {
        asm volatile("cp.async.wait_group %0;" :: "n"(STAGES - 2) : "memory");
        __syncthreads();

        const char* tb = smb + (size_t)(kt & (STAGES - 1)) * STAGE_BYTES;
        #pragma unroll
        for (int ks = 0; ks < 4; ++ks) {
            uint4 a0 = *(const uint4*)(tb + ((wm * 2 + 0) * 4 + ks) * 512 + lane * 16);
            uint4 a1 = *(const uint4*)(tb + ((wm * 2 + 1) * 4 + ks) * 512 + lane * 16);
            uint4 b[4];
            #pragma unroll
            for (int t = 0; t < 4; ++t)
                b[t] = *(const uint4*)(tb + OF_B +
                        ((wn * 4 + t) * 4 + ks) * 512 + lane * 16);
            #pragma unroll
            for (int t = 0; t < 4; ++t) {
                mma_tf32(acc[0][t][0], a0, b[t].x, b[t].y);
                mma_tf32(acc[0][t][1], a0, b[t].z, b[t].w);
                mma_tf32(acc[1][t][0], a1, b[t].x, b[t].y);
                mma_tf32(acc[1][t][1], a1, b[t].z, b[t].w);
            }
        }

        int nk = kt + STAGES - 1;
        if (nk < KTILES) stage(nk, nk & (STAGES - 1));
        asm volatile("cp.async.commit_group;" ::: "memory");
    }

    // epilogue: bias add + float2 stores
    const int g = lane >> 2, q = lane & 3;
    const float* sb = (const float*)(smb + OF_BIAS);
    #pragma unroll
    for (int i = 0; i < 2; ++i) {
        #pragma unroll
        for (int hi = 0; hi < 2; ++hi) {
            int row = m0 + (wm * 2 + i) * 16 + hi * 8 + g;
            float* orow = out + (size_t)row * NEURONS + n0;
            #pragma unroll
            for (int t = 0; t < 4; ++t)
                #pragma unroll
                for (int j = 0; j < 2; ++j) {
                    int col = (wn * 4 + t) * 16 + j * 8 + q * 2;
                    float2 v = make_float2(acc[i][t][j][hi * 2 + 0] + sb[col],
                                           acc[i][t][j][hi * 2 + 1] + sb[col + 1]);
                    *(float2*)(orow + col) = v;
                }
        }
    }
}

// ---------------------------------------------------------------------------
extern "C" void kernel_launch(void* const* d_in, const int* in_sizes, int n_in,
                              void* d_out, int out_size) {
    const float* x    = (const float*)d_in[0];
    const void*  conn = d_in[1];                  // int64 (or int32) indices
    const float* wgt  = (const float*)d_in[2];
    const float* bias = (const float*)d_in[3];
    float* out = (float*)d_out;

    cudaFuncSetAttribute(gemm_tf32,
                         cudaFuncAttributeMaxDynamicSharedMemorySize, SMEM_DYN);
    cudaFuncSetAttribute(densify_W,
                         cudaFuncAttributeMaxDynamicSharedMemorySize,
                         D_SM_FLOATS * 4);
    cudaFuncSetAttribute(round_x_frag,
                         cudaFuncAttributeMaxDynamicSharedMemorySize, R_SM_BYTES);

    round_x_frag<<<32, 256, R_SM_BYTES>>>(x);            // 2 MB, A-fragment order
    densify_W<<<256, 256, D_SM_FLOATS * 4>>>(conn, wgt); // 16 MB, B-fragment order

    dim3 grid(NEURONS / BN, BATCH / BM);                 // 32 x 4 = 128 blocks
    gemm_tf32<<<grid, TPB, SMEM_DYN>>>(bias, out);
}

// round 8
// speedup vs baseline: 2.4009x; 1.0255x over previous
#include <cuda_runtime.h>
#include <stdint.h>

// Problem constants
#define BATCH   512
#define IN_FLAT 1024
#define NEURONS 4096
#define FOCUS   64

// GEMM tiling
#define BM 128
#define BN 128
#define BK 32
#define TPB 128                    // 4 warps (2m x 2n), warp tile 64x64
#define KTILES (IN_FLAT / BK)      // 32
#define STAGES 4
#define STAGE_BYTES 32768          // A 16KB + B 16KB
#define OF_B 16384
#define OF_BIAS (STAGES * STAGE_BYTES)          // 131072
#define SMEM_DYN (OF_BIAS + BN * 4)             // 131584

// Fragment-ordered operands (device globals: no allocation allowed)
// A: [kt 32][m16 32][ks 4][lane 32] float4  (2 MB)
// B: [kt 32][n16 256][ks 4][lane 32] float4 (16 MB)
__device__ float g_xA[BATCH   * IN_FLAT];
__device__ float g_WB[NEURONS * IN_FLAT];

// ---------------------------------------------------------------------------
__device__ __forceinline__ uint32_t smem_u32(const void* p) {
    uint32_t a;
    asm("{ .reg .u64 t; cvta.to.shared.u64 t, %1; cvt.u32.u64 %0, t; }" : "=r"(a) : "l"(p));
    return a;
}
__device__ __forceinline__ float rna_tf32(float f) {
    unsigned u;
    asm("cvt.rna.tf32.f32 %0, %1;" : "=r"(u) : "f"(f));
    return __uint_as_float(u);
}
__device__ __forceinline__ void cp_async16(uint32_t sdst, const void* gsrc) {
    asm volatile("cp.async.cg.shared.global [%0], [%1], 16;"
                 :: "r"(sdst), "l"(__cvta_generic_to_global(gsrc)) : "memory");
}
__device__ __forceinline__ void mma_tf32(float* c, const uint4& a,
                                         uint32_t b0, uint32_t b1) {
    asm volatile(
        "mma.sync.aligned.m16n8k8.row.col.f32.tf32.tf32.f32 "
        "{%0,%1,%2,%3}, {%4,%5,%6,%7}, {%8,%9}, {%0,%1,%2,%3};"
        : "+f"(c[0]), "+f"(c[1]), "+f"(c[2]), "+f"(c[3])
        : "r"(a.x), "r"(a.y), "r"(a.z), "r"(a.w), "r"(b0), "r"(b1));
}

// ---------------------------------------------------------------------------
// Prep 1 (v3): round x to tf32-RN, write A-fragment order.
// 128 blocks: (m16 tile) x (K quarter). 16x256 smem tile, pad stride 260.
#define RSTR 260                               // floats; 260 % 32 = 4
#define R_SM_BYTES (16 * RSTR * 4)             // 16640 B
__global__ void round_x_frag(const float* __restrict__ x) {
    extern __shared__ float ds[];
    const int tid  = threadIdx.x;
    const int lane = tid & 31;
    const int w    = tid >> 5;                 // 8 warps
    const int m16  = blockIdx.x;               // 0..31
    const int kq   = blockIdx.y;               // 0..3, K cols [kq*256, +256)

    // stage rows 2w, 2w+1 of the 16x256 tile (coalesced, rna applied here)
    #pragma unroll
    for (int h = 0; h < 2; ++h) {
        int r = w * 2 + h;
        const float4* src = (const float4*)(x + (size_t)(m16 * 16 + r) * IN_FLAT
                                              + kq * 256);
        float4* dst = (float4*)(ds + r * RSTR);
        #pragma unroll
        for (int j = 0; j < 2; ++j) {
            float4 v = src[j * 32 + lane];
            v.x = rna_tf32(v.x); v.y = rna_tf32(v.y);
            v.z = rna_tf32(v.z); v.w = rna_tf32(v.w);
            dst[j * 32 + lane] = v;
        }
    }
    __syncthreads();

    // write 1024 fragment chunks (4/thread), coalesced STG.128
    #pragma unroll
    for (int i = 0; i < 4; ++i) {
        int e   = i * 256 + tid;               // 0..1023
        int ktl = e >> 7, ks = (e >> 5) & 3, ln = e & 31;
        int ra  = ln >> 2;
        int kl  = ktl * 32 + ks * 8 + (ln & 3);
        float4 v;
        v.x = ds[ra * RSTR + kl];
        v.y = ds[(ra + 8) * RSTR + kl];
        v.z = ds[ra * RSTR + kl + 4];
        v.w = ds[(ra + 8) * RSTR + kl + 4];
        int kt = kq * 8 + ktl;
        ((float4*)g_xA)[((size_t)(kt * 32 + m16) * 4 + ks) * 32 + ln] = v;
    }
}

// Prep 2: densify W in smem (16 rows/block), write in B-fragment order.
#define DSTR 1044                          // padded row stride (floats)
#define D_SM_FLOATS (16 * DSTR)            // 66816 B
__global__ void densify_W(const void* __restrict__ conn_raw,
                          const float* __restrict__ wgt) {
    extern __shared__ float ds[];
    const int tid = threadIdx.x;
    const int n16g = blockIdx.x;           // 0..255

    #pragma unroll
    for (int i = tid; i < D_SM_FLOATS / 4; i += 256)
        ((float4*)ds)[i] = make_float4(0.f, 0.f, 0.f, 0.f);
    __syncthreads();

    const int* c32 = (const int*)conn_raw;
    bool is64 = true;                      // int64 dtype sniff (values < 1024)
    #pragma unroll
    for (int k = 1; k < 64; k += 2) is64 &= (c32[k] == 0);
    const long long* c64 = (const long long*)conn_raw;

    #pragma unroll
    for (int i = 0; i < 4; ++i) {
        int e = i * 256 + tid;                       // 0..1023
        int nl = e >> 6, f = e & 63;
        size_t gi = (size_t)(n16g * 16 + nl) * FOCUS + f;
        int idx = is64 ? (int)c64[gi] : c32[gi];
        atomicAdd(ds + nl * DSTR + idx, rna_tf32(wgt[gi]));
    }
    __syncthreads();

    #pragma unroll
    for (int i = 0; i < 16; ++i) {
        int c   = i * 256 + tid;                     // 0..4095 chunks
        int kt  = c >> 7;
        int rem = c & 127;
        int ks  = rem >> 5, ln = rem & 31;
        int k0  = kt * 32 + ks * 8 + (ln & 3);
        int na  = ln >> 2;
        float4 v;
        v.x = rna_tf32(ds[na * DSTR + k0]);
        v.y = rna_tf32(ds[na * DSTR + k0 + 4]);
        v.z = rna_tf32(ds[(na + 8) * DSTR + k0]);
        v.w = rna_tf32(ds[(na + 8) * DSTR + k0 + 4]);
        ((float4*)g_WB)[(size_t)(kt * 256 + n16g) * 128 + rem] = v;
    }
}

// ---------------------------------------------------------------------------
// Main GEMM: out = x @ W^T + bias. 128 thr (4 warps, 2x2), warp tile 64x64:
// operand duplication minimized -> tensor-bound. cp.async x4, LDS.128 frags.
// ---------------------------------------------------------------------------
__global__ void __launch_bounds__(TPB, 1)
gemm_tf32(const float* __restrict__ bias, float* __restrict__ out) {
    extern __shared__ char smb[];
    const uint32_t sbase = smem_u32(smb);

    const int tid  = threadIdx.x;
    const int lane = tid & 31;
    const int wid  = tid >> 5;
    const int wm   = wid & 1;          // warp row -> m16 tiles {4wm..4wm+3}
    const int wn   = wid >> 1;         // warp col -> n16 tiles {4wn..4wn+3}
    const int n0   = blockIdx.x * BN;
    const int m0   = blockIdx.y * BM;

    *(float*)(smb + OF_BIAS + tid * 4) = bias[n0 + tid];

    const float4* gA4 = (const float4*)g_xA;
    const float4* gB4 = (const float4*)g_WB;
    const int mSlab = m0 >> 4;
    const int nSlab = n0 >> 4;

    auto stage = [&](int kt, int s) {
        uint32_t db = sbase + (uint32_t)s * STAGE_BYTES;
        size_t baseA = ((size_t)kt * 32  + mSlab) * 128;
        size_t baseB = ((size_t)kt * 256 + nSlab) * 128;
        #pragma unroll
        for (int it = 0; it < 8; ++it) {
            cp_async16(db + (uint32_t)(it * 128 + tid) * 16,
                       gA4 + baseA + it * 128 + tid);
            cp_async16(db + OF_B + (uint32_t)(it * 128 + tid) * 16,
                       gB4 + baseB + it * 128 + tid);
        }
    };

    #pragma unroll
    for (int s = 0; s < STAGES - 1; ++s) {
        stage(s, s);
        asm volatile("cp.async.commit_group;" ::: "memory");
    }

    float acc[4][4][2][4] = {};   // [m16 i][n16 t][n8 j][c-reg]

    for (int kt = 0; kt < KTILES; ++kt) {
        asm volatile("cp.async.wait_group %0;" :: "n"(STAGES - 2) : "memory");
        __syncthreads();

        const char* tb = smb + (size_t)(kt & (STAGES - 1)) * STAGE_BYTES;
        #pragma unroll
        for (int ks = 0; ks < 4; ++ks) {
            uint4 a[4], b[4];
            #pragma unroll
            for (int i = 0; i < 4; ++i)
                a[i] = *(const uint4*)(tb + ((wm * 4 + i) * 4 + ks) * 512 + lane * 16);
            #pragma unroll
            for (int t = 0; t < 4; ++t)
                b[t] = *(const uint4*)(tb + OF_B +
                        ((wn * 4 + t) * 4 + ks) * 512 + lane * 16);
            #pragma unroll
            for (int i = 0; i < 4; ++i)
                #pragma unroll
                for (int t = 0; t < 4; ++t) {
                    mma_tf32(acc[i][t][0], a[i], b[t].x, b[t].y);
                    mma_tf32(acc[i][t][1], a[i], b[t].z, b[t].w);
                }
        }

        int nk = kt + STAGES - 1;
        if (nk < KTILES) stage(nk, nk & (STAGES - 1));
        asm volatile("cp.async.commit_group;" ::: "memory");
    }

    // epilogue: bias add + float2 stores
    const int g = lane >> 2, q = lane & 3;
    const float* sb = (const float*)(smb + OF_BIAS);
    #pragma unroll
    for (int i = 0; i < 4; ++i) {
        #pragma unroll
        for (int hi = 0; hi < 2; ++hi) {
            int row = m0 + (wm * 4 + i) * 16 + hi * 8 + g;
            float* orow = out + (size_t)row * NEURONS + n0;
            #pragma unroll
            for (int t = 0; t < 4; ++t)
                #pragma unroll
                for (int j = 0; j < 2; ++j) {
                    int col = (wn * 4 + t) * 16 + j * 8 + q * 2;
                    float2 v = make_float2(acc[i][t][j][hi * 2 + 0] + sb[col],
                                           acc[i][t][j][hi * 2 + 1] + sb[col + 1]);
                    *(float2*)(orow + col) = v;
                }
        }
    }
}

// ---------------------------------------------------------------------------
extern "C" void kernel_launch(void* const* d_in, const int* in_sizes, int n_in,
                              void* d_out, int out_size) {
    const float* x    = (const float*)d_in[0];
    const void*  conn = d_in[1];                  // int64 (or int32) indices
    const float* wgt  = (const float*)d_in[2];
    const float* bias = (const float*)d_in[3];
    float* out = (float*)d_out;

    cudaFuncSetAttribute(gemm_tf32,
                         cudaFuncAttributeMaxDynamicSharedMemorySize, SMEM_DYN);
    cudaFuncSetAttribute(densify_W,
                         cudaFuncAttributeMaxDynamicSharedMemorySize,
                         D_SM_FLOATS * 4);

    dim3 rgrid(32, 4);                                   // 128 blocks
    round_x_frag<<<rgrid, 256, R_SM_BYTES>>>(x);         // 2 MB, A-fragment order
    densify_W<<<256, 256, D_SM_FLOATS * 4>>>(conn, wgt); // 16 MB, B-fragment order

    dim3 grid(NEURONS / BN, BATCH / BM);                 // 32 x 4 = 128 blocks
    gemm_tf32<<<grid, TPB, SMEM_DYN>>>(bias, out);
}

// round 9
// speedup vs baseline: 2.5576x; 1.0653x over previous
#include <cuda_runtime.h>
#include <stdint.h>

// Problem constants
#define BATCH   512
#define IN_FLAT 1024
#define NEURONS 4096
#define FOCUS   64

// GEMM tiling
#define BM 128
#define BN 128
#define BK 64
#define TPB 256                    // 8 warps (2m x 4n), warp tile 64x32
#define KTILES (IN_FLAT / BK)      // 16
#define STAGES 3
#define STAGE_BYTES 65536          // A 32KB + B 32KB
#define OF_B 32768
#define OF_BIAS (STAGES * STAGE_BYTES)          // 196608
#define SMEM_DYN (OF_BIAS + BN * 4)             // 197120

// Fragment-ordered operands (device globals: no allocation allowed)
// A: [kt32 32][m16 32][ks 4][lane 32] float4  (2 MB)
// B: [kt32 32][n16 256][ks 4][lane 32] float4 (16 MB)
__device__ float g_xA[BATCH   * IN_FLAT];
__device__ float g_WB[NEURONS * IN_FLAT];

// ---------------------------------------------------------------------------
__device__ __forceinline__ uint32_t smem_u32(const void* p) {
    uint32_t a;
    asm("{ .reg .u64 t; cvta.to.shared.u64 t, %1; cvt.u32.u64 %0, t; }" : "=r"(a) : "l"(p));
    return a;
}
__device__ __forceinline__ float rna_tf32(float f) {
    unsigned u;
    asm("cvt.rna.tf32.f32 %0, %1;" : "=r"(u) : "f"(f));
    return __uint_as_float(u);
}
__device__ __forceinline__ void cp_async16(uint32_t sdst, const void* gsrc) {
    asm volatile("cp.async.cg.shared.global [%0], [%1], 16;"
                 :: "r"(sdst), "l"(__cvta_generic_to_global(gsrc)) : "memory");
}
__device__ __forceinline__ void mma_tf32(float* c, const uint4& a,
                                         uint32_t b0, uint32_t b1) {
    asm volatile(
        "mma.sync.aligned.m16n8k8.row.col.f32.tf32.tf32.f32 "
        "{%0,%1,%2,%3}, {%4,%5,%6,%7}, {%8,%9}, {%0,%1,%2,%3};"
        : "+f"(c[0]), "+f"(c[1]), "+f"(c[2]), "+f"(c[3])
        : "r"(a.x), "r"(a.y), "r"(a.z), "r"(a.w), "r"(b0), "r"(b1));
}

// ---------------------------------------------------------------------------
// Merged prep kernel:
//   blocks [0,256):   densify W (smem scatter) -> g_WB (B-fragment order)
//   blocks [256,768): round x to tf32-RN       -> g_xA (A-fragment order)
// Merging lets the 2 MB x pass hide entirely under the 16 MB W pass.
#define DSTR 1044                          // padded row stride (floats)
#define D_SM_FLOATS (16 * DSTR)            // 66816 B
__global__ void prep(const float* __restrict__ x,
                     const void* __restrict__ conn_raw,
                     const float* __restrict__ wgt) {
    const int tid = threadIdx.x;

    if (blockIdx.x >= 256) {
        // ---- round_x: one float4 fragment chunk per thread
        int c = (blockIdx.x - 256) * 256 + tid;            // 0..131071
        int lane = c & 31, ks = (c >> 5) & 3, m16 = (c >> 7) & 31, kt = c >> 12;
        int ra = m16 * 16 + (lane >> 2);
        int k0 = kt * 32 + ks * 8 + (lane & 3);
        float4 v;
        v.x = rna_tf32(x[(size_t)ra * IN_FLAT + k0]);
        v.y = rna_tf32(x[(size_t)(ra + 8) * IN_FLAT + k0]);
        v.z = rna_tf32(x[(size_t)ra * IN_FLAT + k0 + 4]);
        v.w = rna_tf32(x[(size_t)(ra + 8) * IN_FLAT + k0 + 4]);
        ((float4*)g_xA)[c] = v;
        return;
    }

    // ---- densify: 16 neuron rows per block via smem scatter
    extern __shared__ float ds[];
    const int n16g = blockIdx.x;           // 0..255

    #pragma unroll
    for (int i = tid; i < D_SM_FLOATS / 4; i += 256)
        ((float4*)ds)[i] = make_float4(0.f, 0.f, 0.f, 0.f);
    __syncthreads();

    const int* c32 = (const int*)conn_raw;
    bool is64 = true;                      // int64 dtype sniff (values < 1024)
    #pragma unroll
    for (int k = 1; k < 64; k += 2) is64 &= (c32[k] == 0);
    const long long* c64 = (const long long*)conn_raw;

    #pragma unroll
    for (int i = 0; i < 4; ++i) {
        int e = i * 256 + tid;                       // 0..1023
        int nl = e >> 6, f = e & 63;
        size_t gi = (size_t)(n16g * 16 + nl) * FOCUS + f;
        int idx = is64 ? (int)c64[gi] : c32[gi];
        atomicAdd(ds + nl * DSTR + idx, rna_tf32(wgt[gi]));
    }
    __syncthreads();

    #pragma unroll
    for (int i = 0; i < 16; ++i) {
        int c   = i * 256 + tid;                     // 0..4095 chunks
        int kt  = c >> 7;
        int rem = c & 127;
        int ks  = rem >> 5, ln = rem & 31;
        int k0  = kt * 32 + ks * 8 + (ln & 3);
        int na  = ln >> 2;
        float4 v;
        v.x = rna_tf32(ds[na * DSTR + k0]);
        v.y = rna_tf32(ds[na * DSTR + k0 + 4]);
        v.z = rna_tf32(ds[(na + 8) * DSTR + k0]);
        v.w = rna_tf32(ds[(na + 8) * DSTR + k0 + 4]);
        ((float4*)g_WB)[(size_t)(kt * 256 + n16g) * 128 + rem] = v;
    }
}

// ---------------------------------------------------------------------------
// Main GEMM: out = x @ W^T + bias. 8 warps = 2/SMSP (latency cover),
// warp grid 2m x 4n, warp tile 64x32, BK=64 (16 barriers), cp.async x3.
// Per SMSP per kt: tensor 2048 cyc vs LSU ~640 cyc -> tensor-bound.
// ---------------------------------------------------------------------------
__global__ void __launch_bounds__(TPB, 1)
gemm_tf32(const float* __restrict__ bias, float* __restrict__ out) {
    extern __shared__ char smb[];
    const uint32_t sbase = smem_u32(smb);

    const int tid  = threadIdx.x;
    const int lane = tid & 31;
    const int wid  = tid >> 5;
    const int wm   = wid & 1;          // warp row -> m16 tiles {4wm..4wm+3}
    const int wn   = wid >> 1;         // warp col (4) -> n16 tiles {2wn, 2wn+1}
    const int n0   = blockIdx.x * BN;
    const int m0   = blockIdx.y * BM;

    if (tid < BN) *(float*)(smb + OF_BIAS + tid * 4) = bias[n0 + tid];

    const float4* gA4 = (const float4*)g_xA;
    const float4* gB4 = (const float4*)g_WB;
    const int mSlab = m0 >> 4;
    const int nSlab = n0 >> 4;

    // stage one BK=64 slab = two consecutive kt32 halves, linear copies
    auto stage = [&](int kt, int s) {
        uint32_t db = sbase + (uint32_t)s * STAGE_BYTES;
        #pragma unroll
        for (int h = 0; h < 2; ++h) {
            size_t baseA = ((size_t)(2 * kt + h) * 32  + mSlab) * 128;
            size_t baseB = ((size_t)(2 * kt + h) * 256 + nSlab) * 128;
            #pragma unroll
            for (int it = 0; it < 4; ++it) {
                uint32_t o = (uint32_t)(h * 1024 + it * 256 + tid);
                cp_async16(db + o * 16,        gA4 + baseA + it * 256 + tid);
                cp_async16(db + OF_B + o * 16, gB4 + baseB + it * 256 + tid);
            }
        }
    };

    #pragma unroll
    for (int s = 0; s < STAGES - 1; ++s) {
        stage(s, s);
        asm volatile("cp.async.commit_group;" ::: "memory");
    }

    float acc[4][2][2][4] = {};   // [m16 i][n16 t][n8 j][c-reg]
    int slot = 0;

    for (int kt = 0; kt < KTILES; ++kt) {
        asm volatile("cp.async.wait_group %0;" :: "n"(STAGES - 2) : "memory");
        __syncthreads();

        const char* tb = smb + (size_t)slot * STAGE_BYTES;
        #pragma unroll
        for (int ks2 = 0; ks2 < 8; ++ks2) {
            const int h = ks2 >> 2, ks = ks2 & 3;
            uint4 a[4], b[2];
            #pragma unroll
            for (int i = 0; i < 4; ++i)
                a[i] = *(const uint4*)(tb +
                        (h * 1024 + ((wm * 4 + i) * 4 + ks) * 32 + lane) * 16);
            #pragma unroll
            for (int t = 0; t < 2; ++t)
                b[t] = *(const uint4*)(tb + OF_B +
                        (h * 1024 + ((wn * 2 + t) * 4 + ks) * 32 + lane) * 16);
            #pragma unroll
            for (int i = 0; i < 4; ++i)
                #pragma unroll
                for (int t = 0; t < 2; ++t) {
                    mma_tf32(acc[i][t][0], a[i], b[t].x, b[t].y);
                    mma_tf32(acc[i][t][1], a[i], b[t].z, b[t].w);
                }
        }

        int nk = kt + STAGES - 1;
        if (nk < KTILES) {
            slot = slot == STAGES - 1 ? 0 : slot + 1;   // slot of nk % STAGES == next compute slot? no:
        }
        // recompute compute slot for next kt and stage nk into (nk % STAGES)
        if (nk < KTILES) stage(nk, nk % STAGES);
        asm volatile("cp.async.commit_group;" ::: "memory");
        slot = (kt + 1) % STAGES;
    }

    // epilogue: bias add + float2 stores
    const int g = lane >> 2, q = lane & 3;
    const float* sb = (const float*)(smb + OF_BIAS);
    #pragma unroll
    for (int i = 0; i < 4; ++i) {
        #pragma unroll
        for (int hi = 0; hi < 2; ++hi) {
            int row = m0 + (wm * 4 + i) * 16 + hi * 8 + g;
            float* orow = out + (size_t)row * NEURONS + n0;
            #pragma unroll
            for (int t = 0; t < 2; ++t)
                #pragma unroll
                for (int j = 0; j < 2; ++j) {
                    int col = (wn * 2 + t) * 16 + j * 8 + q * 2;
                    float2 v = make_float2(acc[i][t][j][hi * 2 + 0] + sb[col],
                                           acc[i][t][j][hi * 2 + 1] + sb[col + 1]);
                    *(float2*)(orow + col) = v;
                }
        }
    }
}

// ---------------------------------------------------------------------------
extern "C" void kernel_launch(void* const* d_in, const int* in_sizes, int n_in,
                              void* d_out, int out_size) {
    const float* x    = (const float*)d_in[0];
    const void*  conn = d_in[1];                  // int64 (or int32) indices
    const float* wgt  = (const float*)d_in[2];
    const float* bias = (const float*)d_in[3];
    float* out = (float*)d_out;

    cudaFuncSetAttribute(gemm_tf32,
                         cudaFuncAttributeMaxDynamicSharedMemorySize, SMEM_DYN);
    cudaFuncSetAttribute(prep,
                         cudaFuncAttributeMaxDynamicSharedMemorySize,
                         D_SM_FLOATS * 4);

    prep<<<768, 256, D_SM_FLOATS * 4>>>(x, conn, wgt);   // densify + round merged

    dim3 grid(NEURONS / BN, BATCH / BM);                 // 32 x 4 = 128 blocks
    gemm_tf32<<<grid, TPB, SMEM_DYN>>>(bias, out);
}

// round 10
// speedup vs baseline: 3.7364x; 1.4609x over previous
#include <cuda_runtime.h>
#include <cuda_fp16.h>
#include <stdint.h>

// Problem constants
#define BATCH   512
#define IN_FLAT 1024
#define NEURONS 4096
#define FOCUS   64

// GEMM tiling (fp16 m16n8k16)
#define BM 128
#define BN 128
#define BK 64
#define TPB 256                    // 8 warps (2m x 4n), warp tile 64x32
#define KTILES (IN_FLAT / BK)      // 16
#define STAGES 4
#define STAGE_BYTES 32768          // A 16KB + B 16KB (fp16)
#define OF_B 16384
#define OF_BIAS (STAGES * STAGE_BYTES)          // 131072
#define SMEM_DYN (OF_BIAS + BN * 4)             // 131584

// Fragment-packed operands (uint4 chunks; device globals, no allocation)
// A chunk (kt16, m16, lane) = {a0,a1,a2,a3} of m16n8k16   -> 64*32*32 uint4 = 1 MB
// B chunk (kt16, n16, lane) = {b0,b1 of n8 j0, b0,b1 j1}  -> 64*256*32 uint4 = 8 MB
__device__ uint4 g_xA[64 * 32 * 32];
__device__ uint4 g_WB[64 * 256 * 32];

// ---------------------------------------------------------------------------
__device__ __forceinline__ uint32_t smem_u32(const void* p) {
    uint32_t a;
    asm("{ .reg .u64 t; cvta.to.shared.u64 t, %1; cvt.u32.u64 %0, t; }" : "=r"(a) : "l"(p));
    return a;
}
__device__ __forceinline__ uint32_t pack_h2(float lo, float hi) {
    __half2 h = __floats2half2_rn(lo, hi);
    return *(uint32_t*)&h;
}
__device__ __forceinline__ void cp_async16(uint32_t sdst, const void* gsrc) {
    asm volatile("cp.async.cg.shared.global [%0], [%1], 16;"
                 :: "r"(sdst), "l"(__cvta_generic_to_global(gsrc)) : "memory");
}
__device__ __forceinline__ void mma_f16(float* c, const uint4& a,
                                        uint32_t b0, uint32_t b1) {
    asm volatile(
        "mma.sync.aligned.m16n8k16.row.col.f32.f16.f16.f32 "
        "{%0,%1,%2,%3}, {%4,%5,%6,%7}, {%8,%9}, {%0,%1,%2,%3};"
        : "+f"(c[0]), "+f"(c[1]), "+f"(c[2]), "+f"(c[3])
        : "r"(a.x), "r"(a.y), "r"(a.z), "r"(a.w), "r"(b0), "r"(b1));
}

// ---------------------------------------------------------------------------
// Merged prep kernel:
//   blocks [0,256):   densify W (f32 smem scatter) -> g_WB fp16 fragment chunks
//   blocks [256,512): convert x                    -> g_xA fp16 fragment chunks
#define DSTR 1044                          // padded row stride (floats)
#define D_SM_FLOATS (16 * DSTR)            // 66816 B
__global__ void prep(const float* __restrict__ x,
                     const void* __restrict__ conn_raw,
                     const float* __restrict__ wgt) {
    const int tid = threadIdx.x;

    if (blockIdx.x >= 256) {
        // ---- x -> A fragment chunk (one uint4 per thread)
        int c = (blockIdx.x - 256) * 256 + tid;            // 0..65535
        int lane = c & 31, m16 = (c >> 5) & 31, kt16 = c >> 10;
        int g = lane >> 2, t = lane & 3;
        const float* r0 = x + (size_t)(m16 * 16 + g) * IN_FLAT;       // row g
        const float* r1 = r0 + 8 * IN_FLAT;                           // row g+8
        int k0 = kt16 * 16 + 2 * t;
        uint4 v;
        v.x = pack_h2(r0[k0],     r0[k0 + 1]);     // a0
        v.y = pack_h2(r1[k0],     r1[k0 + 1]);     // a1
        v.z = pack_h2(r0[k0 + 8], r0[k0 + 9]);     // a2
        v.w = pack_h2(r1[k0 + 8], r1[k0 + 9]);     // a3
        g_xA[c] = v;
        return;
    }

    // ---- densify: 16 neuron rows per block via f32 smem scatter
    extern __shared__ float ds[];
    const int n16g = blockIdx.x;           // 0..255

    #pragma unroll
    for (int i = tid; i < D_SM_FLOATS / 4; i += 256)
        ((float4*)ds)[i] = make_float4(0.f, 0.f, 0.f, 0.f);
    __syncthreads();

    const int* c32 = (const int*)conn_raw;
    bool is64 = true;                      // int64 dtype sniff (values < 1024)
    #pragma unroll
    for (int k = 1; k < 64; k += 2) is64 &= (c32[k] == 0);
    const long long* c64 = (const long long*)conn_raw;

    #pragma unroll
    for (int i = 0; i < 4; ++i) {
        int e = i * 256 + tid;                       // 0..1023
        int nl = e >> 6, f = e & 63;
        size_t gi = (size_t)(n16g * 16 + nl) * FOCUS + f;
        int idx = is64 ? (int)c64[gi] : c32[gi];
        atomicAdd(ds + nl * DSTR + idx, wgt[gi]);
    }
    __syncthreads();

    // write B fragment chunks: 64 kt16 x 32 lanes for this n16 group
    #pragma unroll
    for (int i = 0; i < 8; ++i) {
        int e    = i * 256 + tid;                    // 0..2047
        int kt16 = e >> 5, ln = e & 31;
        int g = ln >> 2, t = ln & 3;
        int k0 = kt16 * 16 + 2 * t;
        const float* w0 = ds + g * DSTR;             // n8 j0 row (local g)
        const float* w1 = ds + (g + 8) * DSTR;       // n8 j1 row (local g+8)
        uint4 v;
        v.x = pack_h2(w0[k0],     w0[k0 + 1]);       // j0.b0
        v.y = pack_h2(w0[k0 + 8], w0[k0 + 9]);       // j0.b1
        v.z = pack_h2(w1[k0],     w1[k0 + 1]);       // j1.b0
        v.w = pack_h2(w1[k0 + 8], w1[k0 + 9]);       // j1.b1
        g_WB[((size_t)kt16 * 256 + n16g) * 32 + ln] = v;
    }
}

// ---------------------------------------------------------------------------
// Main GEMM: out = x @ W^T + bias, fp16 m16n8k16, f32 accumulate.
// 8 warps (2m x 4n), warp tile 64x32, BK=64, 4-stage cp.async.
// Per block-kt: tensor 1024 cyc, crossbar ~1024 cyc (halved from tf32).
// ---------------------------------------------------------------------------
__global__ void __launch_bounds__(TPB, 1)
gemm_f16(const float* __restrict__ bias, float* __restrict__ out) {
    extern __shared__ char smb[];
    const uint32_t sbase = smem_u32(smb);

    const int tid  = threadIdx.x;
    const int lane = tid & 31;
    const int wid  = tid >> 5;
    const int wm   = wid & 1;          // warp row -> m16 tiles {4wm..4wm+3}
    const int wn   = wid >> 1;         // warp col (4) -> n16 tiles {2wn, 2wn+1}
    const int n0   = blockIdx.x * BN;
    const int m0   = blockIdx.y * BM;

    if (tid < BN) *(float*)(smb + OF_BIAS + tid * 4) = bias[n0 + tid];

    const int mSlab = m0 >> 4;         // base m16 index (8 tiles)
    const int nSlab = n0 >> 4;         // base n16 index (8 tiles)

    // stage one BK=64 slab: A 1024 chunks + B 1024 chunks, smem layout
    // [ks 4][tile 8][lane 32] per operand.
    auto stage = [&](int kt, int s) {
        uint32_t db = sbase + (uint32_t)s * STAGE_BYTES;
        #pragma unroll
        for (int it = 0; it < 4; ++it) {
            int c   = it * 256 + tid;                 // 0..1023
            int ks  = c >> 8, tl = (c >> 5) & 7, ln = c & 31;
            int kt16 = kt * 4 + ks;
            cp_async16(db + (uint32_t)c * 16,
                       g_xA + ((size_t)kt16 * 32 + mSlab + tl) * 32 + ln);
            cp_async16(db + OF_B + (uint32_t)c * 16,
                       g_WB + ((size_t)kt16 * 256 + nSlab + tl) * 32 + ln);
        }
    };

    #pragma unroll
    for (int s = 0; s < STAGES - 1; ++s) {
        stage(s, s);
        asm volatile("cp.async.commit_group;" ::: "memory");
    }

    float acc[4][2][2][4] = {};   // [m16 i][n16 t][n8 j][c-reg]

    for (int kt = 0; kt < KTILES; ++kt) {
        asm volatile("cp.async.wait_group %0;" :: "n"(STAGES - 2) : "memory");
        __syncthreads();

        const char* tb = smb + (size_t)(kt & (STAGES - 1)) * STAGE_BYTES;
        #pragma unroll
        for (int ks = 0; ks < 4; ++ks) {
            uint4 a[4], b[2];
            #pragma unroll
            for (int i = 0; i < 4; ++i)
                a[i] = *(const uint4*)(tb + ((ks * 8 + wm * 4 + i) * 32 + lane) * 16);
            #pragma unroll
            for (int t = 0; t < 2; ++t)
                b[t] = *(const uint4*)(tb + OF_B +
                        ((ks * 8 + wn * 2 + t) * 32 + lane) * 16);
            #pragma unroll
            for (int i = 0; i < 4; ++i)
                #pragma unroll
                for (int t = 0; t < 2; ++t) {
                    mma_f16(acc[i][t][0], a[i], b[t].x, b[t].y);
                    mma_f16(acc[i][t][1], a[i], b[t].z, b[t].w);
                }
        }

        int nk = kt + STAGES - 1;
        if (nk < KTILES) stage(nk, nk & (STAGES - 1));
        asm volatile("cp.async.commit_group;" ::: "memory");
    }

    // epilogue: bias add + float2 stores
    const int g = lane >> 2, q = lane & 3;
    const float* sb = (const float*)(smb + OF_BIAS);
    #pragma unroll
    for (int i = 0; i < 4; ++i) {
        #pragma unroll
        for (int hi = 0; hi < 2; ++hi) {
            int row = m0 + (wm * 4 + i) * 16 + hi * 8 + g;
            float* orow = out + (size_t)row * NEURONS + n0;
            #pragma unroll
            for (int t = 0; t < 2; ++t)
                #pragma unroll
                for (int j = 0; j < 2; ++j) {
                    int col = (wn * 2 + t) * 16 + j * 8 + q * 2;
                    float2 v = make_float2(acc[i][t][j][hi * 2 + 0] + sb[col],
                                           acc[i][t][j][hi * 2 + 1] + sb[col + 1]);
                    *(float2*)(orow + col) = v;
                }
        }
    }
}

// ---------------------------------------------------------------------------
extern "C" void kernel_launch(void* const* d_in, const int* in_sizes, int n_in,
                              void* d_out, int out_size) {
    const float* x    = (const float*)d_in[0];
    const void*  conn = d_in[1];                  // int64 (or int32) indices
    const float* wgt  = (const float*)d_in[2];
    const float* bias = (const float*)d_in[3];
    float* out = (float*)d_out;

    cudaFuncSetAttribute(gemm_f16,
                         cudaFuncAttributeMaxDynamicSharedMemorySize, SMEM_DYN);
    cudaFuncSetAttribute(prep,
                         cudaFuncAttributeMaxDynamicSharedMemorySize,
                         D_SM_FLOATS * 4);

    prep<<<512, 256, D_SM_FLOATS * 4>>>(x, conn, wgt);   // densify + convert

    dim3 grid(NEURONS / BN, BATCH / BM);                 // 32 x 4 = 128 blocks
    gemm_f16<<<grid, TPB, SMEM_DYN>>>(bias, out);
}

// round 11
// speedup vs baseline: 3.8803x; 1.0385x over previous
#include <cuda_runtime.h>
#include <cuda_fp16.h>
#include <stdint.h>

// Problem constants
#define BATCH   512
#define IN_FLAT 1024
#define NEURONS 4096
#define FOCUS   64

// GEMM tiling (fp16 m16n8k16)
#define BM 128
#define BN 128
#define BK 128
#define TPB 128                    // 4 warps (2m x 2n), warp tile 64x64
#define KTILES (IN_FLAT / BK)      // 8
#define STAGES 3
#define STAGE_BYTES 65536          // A 32KB + B 32KB (fp16)
#define OF_B 32768
#define OF_BIAS (STAGES * STAGE_BYTES)          // 196608
#define SMEM_DYN (OF_BIAS + BN * 4)             // 197120

// Fragment-packed operands (uint4 chunks; device globals, no allocation)
// A chunk (kt16, m16, lane) = {a0,a1,a2,a3} of m16n8k16   -> 64*32*32 uint4 = 1 MB
// B chunk (kt16, n16, lane) = {b0,b1 of n8 j0, b0,b1 j1}  -> 64*256*32 uint4 = 8 MB
__device__ uint4 g_xA[64 * 32 * 32];
__device__ uint4 g_WB[64 * 256 * 32];

// ---------------------------------------------------------------------------
__device__ __forceinline__ uint32_t smem_u32(const void* p) {
    uint32_t a;
    asm("{ .reg .u64 t; cvta.to.shared.u64 t, %1; cvt.u32.u64 %0, t; }" : "=r"(a) : "l"(p));
    return a;
}
__device__ __forceinline__ uint32_t pack_h2(float lo, float hi) {
    __half2 h = __floats2half2_rn(lo, hi);
    return *(uint32_t*)&h;
}
__device__ __forceinline__ void cp_async16(uint32_t sdst, const void* gsrc) {
    asm volatile("cp.async.cg.shared.global [%0], [%1], 16;"
                 :: "r"(sdst), "l"(__cvta_generic_to_global(gsrc)) : "memory");
}
__device__ __forceinline__ void mma_f16(float* c, const uint4& a,
                                        uint32_t b0, uint32_t b1) {
    asm volatile(
        "mma.sync.aligned.m16n8k16.row.col.f32.f16.f16.f32 "
        "{%0,%1,%2,%3}, {%4,%5,%6,%7}, {%8,%9}, {%0,%1,%2,%3};"
        : "+f"(c[0]), "+f"(c[1]), "+f"(c[2]), "+f"(c[3])
        : "r"(a.x), "r"(a.y), "r"(a.z), "r"(a.w), "r"(b0), "r"(b1));
}

// ---------------------------------------------------------------------------
// Merged prep kernel (512 threads/block):
//   blocks [0,256):   densify W (f32 smem scatter) -> g_WB fp16 fragment chunks
//   blocks [256,384): convert x                    -> g_xA fp16 fragment chunks
#define DSTR 1044                          // padded row stride (floats)
#define D_SM_FLOATS (16 * DSTR)            // 66816 B
__global__ void prep(const float* __restrict__ x,
                     const void* __restrict__ conn_raw,
                     const float* __restrict__ wgt) {
    const int tid = threadIdx.x;

    if (blockIdx.x >= 256) {
        // ---- x -> A fragment chunk (one uint4 per thread)
        int c = (blockIdx.x - 256) * 512 + tid;            // 0..65535
        int lane = c & 31, m16 = (c >> 5) & 31, kt16 = c >> 10;
        int g = lane >> 2, t = lane & 3;
        const float* r0 = x + (size_t)(m16 * 16 + g) * IN_FLAT;       // row g
        const float* r1 = r0 + 8 * IN_FLAT;                           // row g+8
        int k0 = kt16 * 16 + 2 * t;
        uint4 v;
        v.x = pack_h2(r0[k0],     r0[k0 + 1]);     // a0
        v.y = pack_h2(r1[k0],     r1[k0 + 1]);     // a1
        v.z = pack_h2(r0[k0 + 8], r0[k0 + 9]);     // a2
        v.w = pack_h2(r1[k0 + 8], r1[k0 + 9]);     // a3
        g_xA[c] = v;
        return;
    }

    // ---- densify: 16 neuron rows per block via f32 smem scatter
    extern __shared__ float ds[];
    const int n16g = blockIdx.x;           // 0..255

    for (int i = tid; i < D_SM_FLOATS / 4; i += 512)
        ((float4*)ds)[i] = make_float4(0.f, 0.f, 0.f, 0.f);
    __syncthreads();

    const int* c32 = (const int*)conn_raw;
    bool is64 = true;                      // int64 dtype sniff (values < 1024)
    #pragma unroll
    for (int k = 1; k < 64; k += 2) is64 &= (c32[k] == 0);
    const long long* c64 = (const long long*)conn_raw;

    #pragma unroll
    for (int i = 0; i < 2; ++i) {
        int e = i * 512 + tid;                       // 0..1023
        int nl = e >> 6, f = e & 63;
        size_t gi = (size_t)(n16g * 16 + nl) * FOCUS + f;
        int idx = is64 ? (int)c64[gi] : c32[gi];
        atomicAdd(ds + nl * DSTR + idx, wgt[gi]);
    }
    __syncthreads();

    // write B fragment chunks: 64 kt16 x 32 lanes for this n16 group
    #pragma unroll
    for (int i = 0; i < 4; ++i) {
        int e    = i * 512 + tid;                    // 0..2047
        int kt16 = e >> 5, ln = e & 31;
        int g = ln >> 2, t = ln & 3;
        int k0 = kt16 * 16 + 2 * t;
        const float* w0 = ds + g * DSTR;             // n8 j0 row (local g)
        const float* w1 = ds + (g + 8) * DSTR;       // n8 j1 row (local g+8)
        uint4 v;
        v.x = pack_h2(w0[k0],     w0[k0 + 1]);       // j0.b0
        v.y = pack_h2(w0[k0 + 8], w0[k0 + 9]);       // j0.b1
        v.z = pack_h2(w1[k0],     w1[k0 + 1]);       // j1.b0
        v.w = pack_h2(w1[k0 + 8], w1[k0 + 9]);       // j1.b1
        g_WB[((size_t)kt16 * 256 + n16g) * 32 + ln] = v;
    }
}

// ---------------------------------------------------------------------------
// Main GEMM: out = x @ W^T + bias, fp16 m16n8k16, f32 accumulate.
// 4 warps (2x2), warp tile 64x64, BK=128 (8 barriers), 3-stage cp.async.
// Per block-kt: tensor 2048 cyc vs crossbar ~1536 -> tensor-bound (0.75).
// Per ks: 8 independent LDS.128 + 32 independent HMMAs (deep intra-warp ILP).
// ---------------------------------------------------------------------------
__global__ void __launch_bounds__(TPB, 1)
gemm_f16(const float* __restrict__ bias, float* __restrict__ out) {
    extern __shared__ char smb[];
    const uint32_t sbase = smem_u32(smb);

    const int tid  = threadIdx.x;
    const int lane = tid & 31;
    const int wid  = tid >> 5;
    const int wm   = wid & 1;          // warp row -> m16 tiles {4wm..4wm+3}
    const int wn   = wid >> 1;         // warp col -> n16 tiles {4wn..4wn+3}
    const int n0   = blockIdx.x * BN;
    const int m0   = blockIdx.y * BM;

    *(float*)(smb + OF_BIAS + tid * 4) = bias[n0 + tid];

    const int mSlab = m0 >> 4;         // base m16 index (8 tiles)
    const int nSlab = n0 >> 4;         // base n16 index (8 tiles)

    // stage one BK=128 slab: A 2048 chunks + B 2048 chunks.
    // smem layout per operand: [ks 8][tile 8][lane 32] uint4.
    auto stage = [&](int kt, int s) {
        uint32_t db = sbase + (uint32_t)s * STAGE_BYTES;
        #pragma unroll
        for (int it = 0; it < 16; ++it) {
            int c    = it * 128 + tid;               // 0..2047
            int ks   = c >> 8, tl = (c >> 5) & 7, ln = c & 31;
            int kt16 = kt * 8 + ks;
            cp_async16(db + (uint32_t)c * 16,
                       g_xA + ((size_t)kt16 * 32 + mSlab + tl) * 32 + ln);
            cp_async16(db + OF_B + (uint32_t)c * 16,
                       g_WB + ((size_t)kt16 * 256 + nSlab + tl) * 32 + ln);
        }
    };

    #pragma unroll
    for (int s = 0; s < STAGES - 1; ++s) {
        stage(s, s);
        asm volatile("cp.async.commit_group;" ::: "memory");
    }

    float acc[4][4][2][4] = {};   // [m16 i][n16 t][n8 j][c-reg]
    int slot = 0;

    for (int kt = 0; kt < KTILES; ++kt) {
        asm volatile("cp.async.wait_group %0;" :: "n"(STAGES - 2) : "memory");
        __syncthreads();

        const char* tb = smb + (size_t)slot * STAGE_BYTES;
        #pragma unroll
        for (int ks = 0; ks < 8; ++ks) {
            uint4 a[4], b[4];
            #pragma unroll
            for (int i = 0; i < 4; ++i)
                a[i] = *(const uint4*)(tb + ((ks * 8 + wm * 4 + i) * 32 + lane) * 16);
            #pragma unroll
            for (int t = 0; t < 4; ++t)
                b[t] = *(const uint4*)(tb + OF_B +
                        ((ks * 8 + wn * 4 + t) * 32 + lane) * 16);
            #pragma unroll
            for (int i = 0; i < 4; ++i)
                #pragma unroll
                for (int t = 0; t < 4; ++t) {
                    mma_f16(acc[i][t][0], a[i], b[t].x, b[t].y);
                    mma_f16(acc[i][t][1], a[i], b[t].z, b[t].w);
                }
        }

        int nk = kt + STAGES - 1;
        if (nk < KTILES) stage(nk, nk % STAGES);
        asm volatile("cp.async.commit_group;" ::: "memory");
        slot = slot == STAGES - 1 ? 0 : slot + 1;
    }

    // epilogue: bias add + float2 stores
    const int g = lane >> 2, q = lane & 3;
    const float* sb = (const float*)(smb + OF_BIAS);
    #pragma unroll
    for (int i = 0; i < 4; ++i) {
        #pragma unroll
        for (int hi = 0; hi < 2; ++hi) {
            int row = m0 + (wm * 4 + i) * 16 + hi * 8 + g;
            float* orow = out + (size_t)row * NEURONS + n0;
            #pragma unroll
            for (int t = 0; t < 4; ++t)
                #pragma unroll
                for (int j = 0; j < 2; ++j) {
                    int col = (wn * 4 + t) * 16 + j * 8 + q * 2;
                    float2 v = make_float2(acc[i][t][j][hi * 2 + 0] + sb[col],
                                           acc[i][t][j][hi * 2 + 1] + sb[col + 1]);
                    *(float2*)(orow + col) = v;
                }
        }
    }
}

// ---------------------------------------------------------------------------
extern "C" void kernel_launch(void* const* d_in, const int* in_sizes, int n_in,
                              void* d_out, int out_size) {
    const float* x    = (const float*)d_in[0];
    const void*  conn = d_in[1];                  // int64 (or int32) indices
    const float* wgt  = (const float*)d_in[2];
    const float* bias = (const float*)d_in[3];
    float* out = (float*)d_out;

    cudaFuncSetAttribute(gemm_f16,
                         cudaFuncAttributeMaxDynamicSharedMemorySize, SMEM_DYN);
    cudaFuncSetAttribute(prep,
                         cudaFuncAttributeMaxDynamicSharedMemorySize,
                         D_SM_FLOATS * 4);

    prep<<<384, 512, D_SM_FLOATS * 4>>>(x, conn, wgt);   // densify + convert

    dim3 grid(NEURONS / BN, BATCH / BM);                 // 32 x 4 = 128 blocks
    gemm_f16<<<grid, TPB, SMEM_DYN>>>(bias, out);
}